// round 16
// baseline (speedup 1.0000x reference)
#include <cuda_runtime.h>
#include <cuda_fp16.h>
#include <cstdint>

// Problem constants
#define SEQ    4096     // H*W
#define DMODEL 512
#define NHEADS 8
#define DHEAD  64
#define CAN    64       // canvas H = W
#define BATCH  2

typedef unsigned int u32;
typedef unsigned long long u64;
typedef unsigned short u16;

// Scratch (device globals: allocation-free rule)
__device__ float g_qkv[BATCH * SEQ * 3 * DMODEL];            // fp32 [b,s,1536]
__device__ __half g_xh[BATCH * SEQ * DMODEL];                // x fp16
__device__ __half g_wqh[3 * DMODEL * DMODEL];                // w_qkv fp16
__device__ __half g_woh[DMODEL * DMODEL];                    // w_out fp16
__device__ __half g_ath[BATCH * SEQ * DMODEL];               // attn out fp16

__device__ __forceinline__ u32 smem_u32(const void* p) {
    u32 a;
    asm("{ .reg .u64 t; cvta.to.shared.u64 t, %1; cvt.u32.u64 %0, t; }" : "=r"(a) : "l"(p));
    return a;
}
__device__ __forceinline__ u16 hfbits(__half h) { return *(u16*)&h; }

// ---------------------------------------------------------------------------
// fused split: x, w_qkv, w_out -> fp16 (one launch)
// ---------------------------------------------------------------------------
#define N4_X  (BATCH * SEQ * DMODEL / 4)
#define N4_WQ (3 * DMODEL * DMODEL / 4)
#define N4_WO (DMODEL * DMODEL / 4)

__global__ __launch_bounds__(256) void split_all_kernel(const float* __restrict__ x,
                                                        const float* __restrict__ wq,
                                                        const float* __restrict__ wo)
{
    int i = blockIdx.x * 256 + threadIdx.x;
    const float* in;
    __half* dst;
    if (i < N4_X)                   { in = x;  dst = g_xh; }
    else if ((i -= N4_X) < N4_WQ)   { in = wq; dst = g_wqh; }
    else if ((i -= N4_WQ) < N4_WO)  { in = wo; dst = g_woh; }
    else return;

    float4 f = ((const float4*)in)[i];
    float v[4] = {f.x, f.y, f.z, f.w};
    ushort4 hv;
    u16* hp = &hv.x;
#pragma unroll
    for (int j = 0; j < 4; j++) hp[j] = hfbits(__float2half_rn(v[j]));
    ((ushort4*)dst)[i] = hv;
}

// ---------------------------------------------------------------------------
// Plain fp16 GEMM (round-15 winner): C[M,N] = A[M,K] @ B[N,K]^T
// 64x128 CTA tile, 256 threads, warp tile 32x32, 3-stage cp.async, 3 CTAs/SM.
// ---------------------------------------------------------------------------
#define TILE_A  4096
#define STAGEB  12288
#define STAGES  3
#define GEMM_SMEM (STAGES * STAGEB)   // 36864 B

__device__ __forceinline__ void ldsm_x4(u32& r0, u32& r1, u32& r2, u32& r3, u32 addr) {
    asm volatile("ldmatrix.sync.aligned.m8n8.x4.shared.b16 {%0,%1,%2,%3}, [%4];"
                 : "=r"(r0), "=r"(r1), "=r"(r2), "=r"(r3) : "r"(addr));
}
__device__ __forceinline__ void mma_fp16(float* c, const u32* a, u32 b0, u32 b1) {
    asm volatile("mma.sync.aligned.m16n8k16.row.col.f32.f16.f16.f32 "
                 "{%0,%1,%2,%3}, {%4,%5,%6,%7}, {%8,%9}, {%0,%1,%2,%3};"
                 : "+f"(c[0]), "+f"(c[1]), "+f"(c[2]), "+f"(c[3])
                 : "r"(a[0]), "r"(a[1]), "r"(a[2]), "r"(a[3]), "r"(b0), "r"(b1));
}
__device__ __forceinline__ void cp16(u32 daddr, const void* src) {
    asm volatile("cp.async.cg.shared.global [%0], [%1], 16;" :: "r"(daddr), "l"(src));
}

__global__ __launch_bounds__(256, 3)
void gemm_mma(const __half* __restrict__ A, const __half* __restrict__ B,
              float* __restrict__ C, int M, int N, int K)
{
    extern __shared__ char smc[];
    const u32 sb = smem_u32(smc);

    const int tid  = threadIdx.x;
    const int wid  = tid >> 5, lane = tid & 31;
    const int wm   = wid & 1;
    const int wn   = wid >> 1;
    const int bm   = blockIdx.y * 64;
    const int bn   = blockIdx.x * 128;

    const int ra  = lane & 15;
    const int ca  = lane >> 4;
    const int swa = (ra >> 1) & 3;
    const int rb  = (lane & 7) + ((lane >> 4) & 1) * 8;
    const int cbv = (lane >> 3) & 1;
    const int swb = (rb >> 1) & 3;

    const int lrow = tid >> 2;
    const int lc   = tid & 3;
    const u32 lsw  = (u32)((lc ^ ((lrow >> 1) & 3)) * 16);
    const u32 ldoff = (u32)lrow * 64u + lsw;

    float acc[2][4][4];
#pragma unroll
    for (int i = 0; i < 2; i++)
#pragma unroll
        for (int j = 0; j < 4; j++)
#pragma unroll
            for (int r = 0; r < 4; r++) acc[i][j][r] = 0.f;

    const int NC = K / 32;

#define LOAD_CHUNK(kc, stg)                                                        \
    {                                                                              \
        const u32 stbase = sb + (u32)(stg) * STAGEB;                               \
        const __half* a_p = A + (size_t)(bm + lrow) * K + (kc) + lc * 8;           \
        const __half* b_p = B + (size_t)(bn + lrow) * K + (kc) + lc * 8;           \
        cp16(stbase + ldoff, a_p);                                                 \
        cp16(stbase + TILE_A + ldoff, b_p);                                        \
        cp16(stbase + TILE_A + 4096u + ldoff, b_p + (size_t)64 * K);               \
    }

    LOAD_CHUNK(0, 0);
    asm volatile("cp.async.commit_group;" ::: "memory");
    LOAD_CHUNK(32, 1);
    asm volatile("cp.async.commit_group;" ::: "memory");

    int st = 0, ldst = 2;
    for (int ch = 0; ch < NC; ch++) {
        asm volatile("cp.async.wait_group %0;" :: "n"(1) : "memory");
        __syncthreads();

        if (ch + 2 < NC) {
            LOAD_CHUNK((ch + 2) * 32, ldst);
            if (++ldst == STAGES) ldst = 0;
        }
        asm volatile("cp.async.commit_group;" ::: "memory");

        const u32 stb = sb + (u32)st * STAGEB;
        if (++st == STAGES) st = 0;
#pragma unroll
        for (int ks = 0; ks < 2; ks++) {
            u32 ah[2][4];
#pragma unroll
            for (int mt = 0; mt < 2; mt++) {
                const u32 arow = (u32)(wm * 32 + mt * 16 + ra);
                const u32 acb  = (u32)(((ks * 2 + ca) ^ swa) * 16);
                ldsm_x4(ah[mt][0], ah[mt][1], ah[mt][2], ah[mt][3],
                        stb + arow * 64 + acb);
            }
#pragma unroll
            for (int p = 0; p < 2; p++) {
                u32 bh[4];
                const u32 brow = (u32)(wn * 32 + p * 16 + rb);
                const u32 bcb  = (u32)(((ks * 2 + cbv) ^ swb) * 16);
                ldsm_x4(bh[0], bh[1], bh[2], bh[3],
                        stb + TILE_A + brow * 64 + bcb);
#pragma unroll
                for (int mt = 0; mt < 2; mt++)
#pragma unroll
                    for (int h = 0; h < 2; h++)
                        mma_fp16(acc[mt][p * 2 + h], ah[mt], bh[h * 2], bh[h * 2 + 1]);
            }
        }
    }

    const int qrow = lane >> 2;
    const int qcol = (lane & 3) * 2;
#pragma unroll
    for (int mt = 0; mt < 2; mt++)
#pragma unroll
        for (int nt = 0; nt < 4; nt++) {
            const int r0 = bm + wm * 32 + mt * 16 + qrow;
            const int cc = bn + wn * 32 + nt * 8 + qcol;
            float2 lo0 = {acc[mt][nt][0], acc[mt][nt][1]};
            float2 lo1 = {acc[mt][nt][2], acc[mt][nt][3]};
            *(float2*)(C + (size_t)r0 * N + cc)       = lo0;
            *(float2*)(C + (size_t)(r0 + 8) * N + cc) = lo1;
        }
#undef LOAD_CHUNK
}

// ---------------------------------------------------------------------------
// packed fp32x2 helpers
// ---------------------------------------------------------------------------
__device__ __forceinline__ u64 pack2(float lo, float hi) {
    u64 r; asm("mov.b64 %0, {%1, %2};" : "=l"(r) : "f"(lo), "f"(hi)); return r;
}
__device__ __forceinline__ u64 dup2(float v) { return pack2(v, v); }
__device__ __forceinline__ void ffma2(u64& acc, u64 a, u64 b) {
    asm("fma.rn.f32x2 %0, %1, %2, %0;" : "+l"(acc) : "l"(a), "l"(b));
}
__device__ __forceinline__ float2 unpk2(u64 v) {
    float2 f; asm("mov.b64 {%0, %1}, %2;" : "=f"(f.x), "=f"(f.y) : "l"(v)); return f;
}

// ---------------------------------------------------------------------------
// Neighborhood attention, PHASE-SPLIT K/V buffer reuse -> 3 CTAs/SM.
//   stage K -> scores (query-pair shared) -> sync -> stage V (same buffer)
//   -> AV (query-pair shared). smem 63.5KB.
// ---------------------------------------------------------------------------
#define KV_W(key, c4) (((key) << 6) + (((c4) ^ ((key) & 15)) << 2))
#define SS_STRIDE 51
#define SMEM_ATTN_BYTES ((196 * 64 + 64 * SS_STRIDE + 64) * 4)   // 63488

__global__ __launch_bounds__(256, 3) void nattn_kernel(const float* __restrict__ qkv,
                                                       __half* __restrict__ oh)
{
    extern __shared__ float smf[];
    float* skv = smf;                      // [196*64] swizzled (K, then V)
    float* ss = smf + 196 * 64;            // [64][SS_STRIDE] (exp values)
    float* swsum = ss + 64 * SS_STRIDE;    // [64] per-query exp sums

    const int th = blockIdx.x >> 3;
    const int tw = blockIdx.x & 7;
    const int nh = blockIdx.y;
    const int b  = blockIdx.z;

    const int sh0 = max(th * 8 - 3, 0);
    const int KH  = min(th * 8 + 4, 57) + 7 - sh0;
    const int sw0 = max(tw * 8 - 3, 0);
    const int KW  = min(tw * 8 + 4, 57) + 7 - sw0;

    const int tid = threadIdx.x;
    const int nk  = KH * KW;

    const float* kbase = qkv + (size_t)b * SEQ * (3 * DMODEL) + DMODEL + nh * DHEAD;
    const float* vbase = kbase + DMODEL;

    // ---- stage K union window (swizzled) ----
    for (int idx = tid; idx < nk * 16; idx += 256) {
        const int key = idx >> 4;
        const int c4  = idx & 15;
        const int kh  = sh0 + key / KW;
        const int kw  = sw0 + key % KW;
        const size_t src = (size_t)(kh * CAN + kw) * (3 * DMODEL) + c4 * 4;
        *(float4*)(skv + KV_W(key, c4)) = *(const float4*)(kbase + src);
    }
    __syncthreads();

    // ================= score phase: query pairs =================
    {
        const int kg  = tid & 7;            // union column
        const int p   = tid >> 3;           // pair 0..31
        const int qy  = p >> 2, qxp = p & 3;
        const int qw0 = tw * 8 + qxp * 2;
        const int qhh = th * 8 + qy;
        const int sH  = min(max(qhh - 3, 0), 57);
        const int sW0 = min(max(qw0 - 3, 0), 57);
        const int sW1 = min(max(qw0 - 2, 0), 57);
        const int dlt = sW1 - sW0;          // 0 or 1
        const int UW  = dlt + 7;
        const int rH  = sH - sh0;
        const int rWu = sW0 - sw0;
        const bool act = (kg < UW);
        const int q0t = qy * 8 + qxp * 2;   // tile-local query index
        const int s_q0 = qhh * CAN + qw0;

        u64 dot0[7], dot1[7];
#pragma unroll
        for (int a = 0; a < 7; a++) { dot0[a] = 0ull; dot1[a] = 0ull; }

        const float4* q0p = (const float4*)(qkv + (size_t)(b * SEQ + s_q0) * (3 * DMODEL)
                                            + nh * DHEAD);
        const float4* q1p = (const float4*)((const float*)q0p + 3 * DMODEL);

#pragma unroll
        for (int dc = 0; dc < 4; dc++) {
            u64 q0c[8], q1c[8];
#pragma unroll
            for (int j = 0; j < 4; j++) {
                float4 f0 = q0p[dc * 4 + j];
                q0c[2 * j]     = pack2(f0.x, f0.y);
                q0c[2 * j + 1] = pack2(f0.z, f0.w);
                float4 f1 = q1p[dc * 4 + j];
                q1c[2 * j]     = pack2(f1.x, f1.y);
                q1c[2 * j + 1] = pack2(f1.z, f1.w);
            }
#pragma unroll
            for (int a = 0; a < 7; a++) {
                if (act) {
                    const int key = (rH + a) * KW + rWu + kg;
#pragma unroll
                    for (int j = 0; j < 4; j++) {
                        float4 k = *(const float4*)(skv + KV_W(key, dc * 4 + j));
                        const u64 kp0 = pack2(k.x, k.y);
                        const u64 kp1 = pack2(k.z, k.w);
                        ffma2(dot0[a], q0c[2 * j],     kp0);
                        ffma2(dot0[a], q0c[2 * j + 1], kp1);
                        ffma2(dot1[a], q1c[2 * j],     kp0);
                        ffma2(dot1[a], q1c[2 * j + 1], kp1);
                    }
                }
            }
        }

        const bool v0 = (kg < 7);
        const bool v1 = (kg >= dlt) && ((kg - dlt) < 7);
        float cs0 = 0.f, cs1 = 0.f;
#pragma unroll
        for (int a = 0; a < 7; a++) {
            float2 s0 = unpk2(dot0[a]);
            float2 s1 = unpk2(dot1[a]);
            if (v0) {
                const float e0 = __expf((s0.x + s0.y) * 0.125f);
                ss[q0t * SS_STRIDE + a * 7 + kg] = e0;
                cs0 += e0;
            }
            if (v1) {
                const float e1 = __expf((s1.x + s1.y) * 0.125f);
                ss[(q0t + 1) * SS_STRIDE + a * 7 + kg - dlt] = e1;
                cs1 += e1;
            }
        }
        cs0 += __shfl_xor_sync(0xffffffffu, cs0, 1);
        cs0 += __shfl_xor_sync(0xffffffffu, cs0, 2);
        cs0 += __shfl_xor_sync(0xffffffffu, cs0, 4);
        cs1 += __shfl_xor_sync(0xffffffffu, cs1, 1);
        cs1 += __shfl_xor_sync(0xffffffffu, cs1, 2);
        cs1 += __shfl_xor_sync(0xffffffffu, cs1, 4);
        if (kg == 0) {
            swsum[q0t]     = cs0;
            swsum[q0t + 1] = cs1;
        }
    }
    __syncthreads();

    // ---- stage V union window into the SAME buffer ----
    for (int idx = tid; idx < nk * 16; idx += 256) {
        const int key = idx >> 4;
        const int c4  = idx & 15;
        const int kh  = sh0 + key / KW;
        const int kw  = sw0 + key % KW;
        const size_t src = (size_t)(kh * CAN + kw) * (3 * DMODEL) + c4 * 4;
        *(float4*)(skv + KV_W(key, c4)) = *(const float4*)(vbase + src);
    }
    __syncthreads();

    // ================= AV phase: query pairs =================
    {
        const int sg  = tid & 7;            // 8-dim segment
        const int p   = tid >> 3;           // pair 0..31
        const int qy  = p >> 2, qxp = p & 3;
        const int qw0 = tw * 8 + qxp * 2;
        const int qhh = th * 8 + qy;
        const int sH  = min(max(qhh - 3, 0), 57);
        const int sW0 = min(max(qw0 - 3, 0), 57);
        const int sW1 = min(max(qw0 - 2, 0), 57);
        const int dlt = sW1 - sW0;
        const int UW  = dlt + 7;
        const int rH  = sH - sh0;
        const int rWu = sW0 - sw0;
        const int q0t = qy * 8 + qxp * 2;

        const float inv0 = 1.0f / swsum[q0t];
        const float inv1 = 1.0f / swsum[q0t + 1];

        u64 a0lo[2] = {0ull, 0ull}, a0hi[2] = {0ull, 0ull};
        u64 a1lo[2] = {0ull, 0ull}, a1hi[2] = {0ull, 0ull};

#pragma unroll
        for (int a = 0; a < 7; a++) {
#pragma unroll
            for (int cu = 0; cu < 8; cu++) {
                if (cu < UW) {
                    const int key = (rH + a) * KW + rWu + cu;
                    const float w0 = (cu < 7)
                        ? ss[q0t * SS_STRIDE + a * 7 + cu] : 0.f;
                    const float w1 = (cu >= dlt && (cu - dlt) < 7)
                        ? ss[(q0t + 1) * SS_STRIDE + a * 7 + cu - dlt] : 0.f;
                    const u64 w02 = dup2(w0), w12 = dup2(w1);
                    float4 vlo = *(const float4*)(skv + KV_W(key, sg));
                    float4 vhi = *(const float4*)(skv + KV_W(key, sg + 8));
                    const u64 vl0 = pack2(vlo.x, vlo.y), vl1 = pack2(vlo.z, vlo.w);
                    const u64 vh0 = pack2(vhi.x, vhi.y), vh1 = pack2(vhi.z, vhi.w);
                    ffma2(a0lo[0], w02, vl0); ffma2(a0lo[1], w02, vl1);
                    ffma2(a0hi[0], w02, vh0); ffma2(a0hi[1], w02, vh1);
                    ffma2(a1lo[0], w12, vl0); ffma2(a1lo[1], w12, vl1);
                    ffma2(a1hi[0], w12, vh0); ffma2(a1hi[1], w12, vh1);
                }
            }
        }

        const size_t ob0 = ((size_t)(b * SEQ + qhh * CAN + qw0)) * DMODEL + nh * DHEAD;
        const size_t ob1 = ob0 + DMODEL;    // adjacent query column

#define WRITE4(accA, accB, invv, base)                                      \
        {                                                                   \
            float2 pA = unpk2(accA), pB = unpk2(accB);                      \
            float vv[4] = {pA.x * (invv), pA.y * (invv),                    \
                           pB.x * (invv), pB.y * (invv)};                   \
            ushort4 h4;                                                     \
            u16* hp = &h4.x;                                                \
            _Pragma("unroll")                                               \
            for (int j = 0; j < 4; j++)                                     \
                hp[j] = hfbits(__float2half_rn(vv[j]));                     \
            *(ushort4*)(oh + (base)) = h4;                                  \
        }

        WRITE4(a0lo[0], a0lo[1], inv0, ob0 + sg * 4);
        WRITE4(a0hi[0], a0hi[1], inv0, ob0 + 32 + sg * 4);
        WRITE4(a1lo[0], a1lo[1], inv1, ob1 + sg * 4);
        WRITE4(a1hi[0], a1hi[1], inv1, ob1 + 32 + sg * 4);
#undef WRITE4
    }
}

// ---------------------------------------------------------------------------
extern "C" void kernel_launch(void* const* d_in, const int* in_sizes, int n_in,
                              void* d_out, int out_size)
{
    const float* x     = (const float*)d_in[0];   // [8192,512]
    const float* w_qkv = (const float*)d_in[1];   // [1536,512]
    const float* w_out = (const float*)d_in[2];   // [512,512]
    float* out = (float*)d_out;                   // [8192,512]

    float* qkv;
    __half *xh, *wqh, *woh, *ath;
    cudaGetSymbolAddress((void**)&qkv, g_qkv);
    cudaGetSymbolAddress((void**)&xh,  g_xh);
    cudaGetSymbolAddress((void**)&wqh, g_wqh);
    cudaGetSymbolAddress((void**)&woh, g_woh);
    cudaGetSymbolAddress((void**)&ath, g_ath);

    cudaFuncSetAttribute(gemm_mma, cudaFuncAttributeMaxDynamicSharedMemorySize, GEMM_SMEM);
    cudaFuncSetAttribute(nattn_kernel, cudaFuncAttributeMaxDynamicSharedMemorySize,
                         SMEM_ATTN_BYTES);

    const int M = BATCH * SEQ;  // 8192

    // 0) fused fp16 conversion of x, w_qkv, w_out (single launch)
    {
        const int total = N4_X + N4_WQ + N4_WO;
        split_all_kernel<<<(total + 255) / 256, 256>>>(x, w_qkv, w_out);
    }

    // 1) QKV projection: [8192,1536]
    gemm_mma<<<dim3((3 * DMODEL) / 128, M / 64), 256, GEMM_SMEM>>>(
        xh, wqh, qkv, M, 3 * DMODEL, DMODEL);

    // 2) neighborhood attention -> fp16 [8192,512]
    nattn_kernel<<<dim3(64, NHEADS, BATCH), 256, SMEM_ATTN_BYTES>>>(qkv, ath);

    // 3) output projection: [8192,512]
    gemm_mma<<<dim3(DMODEL / 128, M / 64), 256, GEMM_SMEM>>>(
        ath, woh, out, M, DMODEL, DMODEL);
}

// round 17
// speedup vs baseline: 1.0826x; 1.0826x over previous
#include <cuda_runtime.h>
#include <cuda_fp16.h>
#include <cstdint>

// Problem constants
#define SEQ    4096     // H*W
#define DMODEL 512
#define NHEADS 8
#define DHEAD  64
#define CAN    64       // canvas H = W
#define BATCH  2

typedef unsigned int u32;
typedef unsigned long long u64;
typedef unsigned short u16;

// Scratch (device globals: allocation-free rule)
__device__ float g_qkv[BATCH * SEQ * 3 * DMODEL];            // fp32 [b,s,1536]
__device__ __half g_xh[BATCH * SEQ * DMODEL];                // x fp16
__device__ __half g_wqh[3 * DMODEL * DMODEL];                // w_qkv fp16
__device__ __half g_woh[DMODEL * DMODEL];                    // w_out fp16
__device__ __half g_ath[BATCH * SEQ * DMODEL];               // attn out fp16

__device__ __forceinline__ u32 smem_u32(const void* p) {
    u32 a;
    asm("{ .reg .u64 t; cvta.to.shared.u64 t, %1; cvt.u32.u64 %0, t; }" : "=r"(a) : "l"(p));
    return a;
}
__device__ __forceinline__ u16 hfbits(__half h) { return *(u16*)&h; }

// ---------------------------------------------------------------------------
// fused split: x, w_qkv, w_out -> fp16 (one launch)
// ---------------------------------------------------------------------------
#define N4_X  (BATCH * SEQ * DMODEL / 4)
#define N4_WQ (3 * DMODEL * DMODEL / 4)
#define N4_WO (DMODEL * DMODEL / 4)

__global__ __launch_bounds__(256) void split_all_kernel(const float* __restrict__ x,
                                                        const float* __restrict__ wq,
                                                        const float* __restrict__ wo)
{
    int i = blockIdx.x * 256 + threadIdx.x;
    const float* in;
    __half* dst;
    if (i < N4_X)                   { in = x;  dst = g_xh; }
    else if ((i -= N4_X) < N4_WQ)   { in = wq; dst = g_wqh; }
    else if ((i -= N4_WQ) < N4_WO)  { in = wo; dst = g_woh; }
    else return;

    float4 f = ((const float4*)in)[i];
    float v[4] = {f.x, f.y, f.z, f.w};
    ushort4 hv;
    u16* hp = &hv.x;
#pragma unroll
    for (int j = 0; j < 4; j++) hp[j] = hfbits(__float2half_rn(v[j]));
    ((ushort4*)dst)[i] = hv;
}

// ---------------------------------------------------------------------------
// Plain fp16 GEMM: C[M,N] = A[M,K] @ B[N,K]^T
// 64x128 CTA tile, 256 threads, warp tile 32x32, K-chunk 64, 3-stage cp.async,
// 3 CTAs/SM. Per stage: A(8KB, 64 rows x 128B) | B(16KB, 128 rows x 128B).
// smem rows 128B, 16B-chunk swizzle c ^= row&7.
// ---------------------------------------------------------------------------
#define TILE_A  8192
#define STAGEB  24576
#define STAGES  3
#define GEMM_SMEM (STAGES * STAGEB)   // 73728 B

__device__ __forceinline__ void ldsm_x4(u32& r0, u32& r1, u32& r2, u32& r3, u32 addr) {
    asm volatile("ldmatrix.sync.aligned.m8n8.x4.shared.b16 {%0,%1,%2,%3}, [%4];"
                 : "=r"(r0), "=r"(r1), "=r"(r2), "=r"(r3) : "r"(addr));
}
__device__ __forceinline__ void mma_fp16(float* c, const u32* a, u32 b0, u32 b1) {
    asm volatile("mma.sync.aligned.m16n8k16.row.col.f32.f16.f16.f32 "
                 "{%0,%1,%2,%3}, {%4,%5,%6,%7}, {%8,%9}, {%0,%1,%2,%3};"
                 : "+f"(c[0]), "+f"(c[1]), "+f"(c[2]), "+f"(c[3])
                 : "r"(a[0]), "r"(a[1]), "r"(a[2]), "r"(a[3]), "r"(b0), "r"(b1));
}
__device__ __forceinline__ void cp16(u32 daddr, const void* src) {
    asm volatile("cp.async.cg.shared.global [%0], [%1], 16;" :: "r"(daddr), "l"(src));
}

__global__ __launch_bounds__(256, 3)
void gemm_mma(const __half* __restrict__ A, const __half* __restrict__ B,
              float* __restrict__ C, int M, int N, int K)
{
    extern __shared__ char smc[];
    const u32 sb = smem_u32(smc);

    const int tid  = threadIdx.x;
    const int wid  = tid >> 5, lane = tid & 31;
    const int wm   = wid & 1;          // 2 row halves of 32
    const int wn   = wid >> 1;         // 4 col groups of 32
    const int bm   = blockIdx.y * 64;
    const int bn   = blockIdx.x * 128;

    const int ra  = lane & 15;
    const int ca  = lane >> 4;
    const int rb  = (lane & 7) + ((lane >> 4) & 1) * 8;
    const int cbv = (lane >> 3) & 1;

    float acc[2][4][4];
#pragma unroll
    for (int i = 0; i < 2; i++)
#pragma unroll
        for (int j = 0; j < 4; j++)
#pragma unroll
            for (int r = 0; r < 4; r++) acc[i][j][r] = 0.f;

    const int NC = K / 64;

#define LOAD_CHUNK(kc, stg)                                                        \
    {                                                                              \
        const u32 stbase = sb + (u32)(stg) * STAGEB;                               \
        _Pragma("unroll")                                                          \
        for (int i = 0; i < 6; i++) {                                              \
            const int idx = tid + i * 256;        /* 0..1535 */                    \
            if (idx < 512) {                                                       \
                const int row = idx >> 3, c = idx & 7;                             \
                const u32 dst = stbase + (u32)row * 128u                           \
                                + (u32)((c ^ (row & 7)) << 4);                     \
                cp16(dst, A + (size_t)(bm + row) * K + (kc) + c * 8);              \
            } else {                                                               \
                const int jj = idx - 512;                                          \
                const int row = jj >> 3, c = jj & 7;                               \
                const u32 dst = stbase + TILE_A + (u32)row * 128u                  \
                                + (u32)((c ^ (row & 7)) << 4);                     \
                cp16(dst, B + (size_t)(bn + row) * K + (kc) + c * 8);              \
            }                                                                      \
        }                                                                          \
    }

    LOAD_CHUNK(0, 0);
    asm volatile("cp.async.commit_group;" ::: "memory");
    LOAD_CHUNK(64, 1);
    asm volatile("cp.async.commit_group;" ::: "memory");

    int st = 0, ldst = 2;
    for (int ch = 0; ch < NC; ch++) {
        asm volatile("cp.async.wait_group %0;" :: "n"(1) : "memory");
        __syncthreads();

        if (ch + 2 < NC) {
            LOAD_CHUNK((ch + 2) * 64, ldst);
            if (++ldst == STAGES) ldst = 0;
        }
        asm volatile("cp.async.commit_group;" ::: "memory");

        const u32 stb = sb + (u32)st * STAGEB;
        if (++st == STAGES) st = 0;
#pragma unroll
        for (int ks = 0; ks < 4; ks++) {
            u32 ah[2][4];
#pragma unroll
            for (int mt = 0; mt < 2; mt++) {
                const int arow = wm * 32 + mt * 16 + ra;
                const u32 achk = (u32)(((ks * 2 + ca) ^ (arow & 7)) << 4);
                ldsm_x4(ah[mt][0], ah[mt][1], ah[mt][2], ah[mt][3],
                        stb + (u32)arow * 128u + achk);
            }
#pragma unroll
            for (int p = 0; p < 2; p++) {
                u32 bh[4];
                const int brow = wn * 32 + p * 16 + rb;
                const u32 bchk = (u32)(((ks * 2 + cbv) ^ (brow & 7)) << 4);
                ldsm_x4(bh[0], bh[1], bh[2], bh[3],
                        stb + TILE_A + (u32)brow * 128u + bchk);
#pragma unroll
                for (int mt = 0; mt < 2; mt++)
#pragma unroll
                    for (int h = 0; h < 2; h++)
                        mma_fp16(acc[mt][p * 2 + h], ah[mt], bh[h * 2], bh[h * 2 + 1]);
            }
        }
    }

    const int qrow = lane >> 2;
    const int qcol = (lane & 3) * 2;
#pragma unroll
    for (int mt = 0; mt < 2; mt++)
#pragma unroll
        for (int nt = 0; nt < 4; nt++) {
            const int r0 = bm + wm * 32 + mt * 16 + qrow;
            const int cc = bn + wn * 32 + nt * 8 + qcol;
            float2 lo0 = {acc[mt][nt][0], acc[mt][nt][1]};
            float2 lo1 = {acc[mt][nt][2], acc[mt][nt][3]};
            *(float2*)(C + (size_t)r0 * N + cc)       = lo0;
            *(float2*)(C + (size_t)(r0 + 8) * N + cc) = lo1;
        }
#undef LOAD_CHUNK
}

// ---------------------------------------------------------------------------
// packed fp32x2 helpers
// ---------------------------------------------------------------------------
__device__ __forceinline__ u64 pack2(float lo, float hi) {
    u64 r; asm("mov.b64 %0, {%1, %2};" : "=l"(r) : "f"(lo), "f"(hi)); return r;
}
__device__ __forceinline__ u64 dup2(float v) { return pack2(v, v); }
__device__ __forceinline__ void ffma2(u64& acc, u64 a, u64 b) {
    asm("fma.rn.f32x2 %0, %1, %2, %0;" : "+l"(acc) : "l"(a), "l"(b));
}
__device__ __forceinline__ float2 unpk2(u64 v) {
    float2 f; asm("mov.b64 {%0, %1}, %2;" : "=f"(f.x), "=f"(f.y) : "l"(v)); return f;
}

// ---------------------------------------------------------------------------
// Neighborhood attention (round-15 winner, reverted): XOR-swizzled K/V,
// 2 CTAs/SM, query-pair sharing in BOTH phases, in-phase wsum reduce,
// single fp16 output.
// ---------------------------------------------------------------------------
#define KV_W(key, c4) (((key) << 6) + (((c4) ^ ((key) & 15)) << 2))
#define SS_STRIDE 51
#define SMEM_ATTN_BYTES ((196 * 64 * 2 + 64 * SS_STRIDE + 64) * 4)

__global__ __launch_bounds__(256, 2) void nattn_kernel(const float* __restrict__ qkv,
                                                       __half* __restrict__ oh)
{
    extern __shared__ float smf[];
    float* sk = smf;                       // [196*64] swizzled
    float* sv = smf + 196 * 64;            // [196*64] swizzled
    float* ss = sv + 196 * 64;             // [64][SS_STRIDE] (exp values)
    float* swsum = ss + 64 * SS_STRIDE;    // [64] per-query exp sums

    const int th = blockIdx.x >> 3;
    const int tw = blockIdx.x & 7;
    const int nh = blockIdx.y;
    const int b  = blockIdx.z;

    const int sh0 = max(th * 8 - 3, 0);
    const int KH  = min(th * 8 + 4, 57) + 7 - sh0;
    const int sw0 = max(tw * 8 - 3, 0);
    const int KW  = min(tw * 8 + 4, 57) + 7 - sw0;

    const int tid = threadIdx.x;
    const int nk  = KH * KW;

    const float* kbase = qkv + (size_t)b * SEQ * (3 * DMODEL) + DMODEL + nh * DHEAD;
    const float* vbase = kbase + DMODEL;

    // stage K/V union window (swizzled)
    for (int idx = tid; idx < nk * 16; idx += 256) {
        const int key = idx >> 4;
        const int c4  = idx & 15;
        const int kh  = sh0 + key / KW;
        const int kw  = sw0 + key % KW;
        const size_t src = (size_t)(kh * CAN + kw) * (3 * DMODEL) + c4 * 4;
        float4 kd = *(const float4*)(kbase + src);
        float4 vd = *(const float4*)(vbase + src);
        *(float4*)(sk + KV_W(key, c4)) = kd;
        *(float4*)(sv + KV_W(key, c4)) = vd;
    }
    __syncthreads();

    // ================= score phase: query pairs =================
    {
        const int kg  = tid & 7;            // union column
        const int p   = tid >> 3;           // pair 0..31
        const int qy  = p >> 2, qxp = p & 3;
        const int qw0 = tw * 8 + qxp * 2;
        const int qhh = th * 8 + qy;
        const int sH  = min(max(qhh - 3, 0), 57);
        const int sW0 = min(max(qw0 - 3, 0), 57);
        const int sW1 = min(max(qw0 - 2, 0), 57);
        const int dlt = sW1 - sW0;          // 0 or 1
        const int UW  = dlt + 7;
        const int rH  = sH - sh0;
        const int rWu = sW0 - sw0;
        const bool act = (kg < UW);
        const int q0t = qy * 8 + qxp * 2;   // tile-local query index
        const int s_q0 = qhh * CAN + qw0;

        u64 dot0[7], dot1[7];
#pragma unroll
        for (int a = 0; a < 7; a++) { dot0[a] = 0ull; dot1[a] = 0ull; }

        const float4* q0p = (const float4*)(qkv + (size_t)(b * SEQ + s_q0) * (3 * DMODEL)
                                            + nh * DHEAD);
        const float4* q1p = (const float4*)((const float*)q0p + 3 * DMODEL);

#pragma unroll
        for (int dc = 0; dc < 4; dc++) {
            u64 q0c[8], q1c[8];
#pragma unroll
            for (int j = 0; j < 4; j++) {
                float4 f0 = q0p[dc * 4 + j];
                q0c[2 * j]     = pack2(f0.x, f0.y);
                q0c[2 * j + 1] = pack2(f0.z, f0.w);
                float4 f1 = q1p[dc * 4 + j];
                q1c[2 * j]     = pack2(f1.x, f1.y);
                q1c[2 * j + 1] = pack2(f1.z, f1.w);
            }
#pragma unroll
            for (int a = 0; a < 7; a++) {
                if (act) {
                    const int key = (rH + a) * KW + rWu + kg;
#pragma unroll
                    for (int j = 0; j < 4; j++) {
                        float4 k = *(const float4*)(sk + KV_W(key, dc * 4 + j));
                        const u64 kp0 = pack2(k.x, k.y);
                        const u64 kp1 = pack2(k.z, k.w);
                        ffma2(dot0[a], q0c[2 * j],     kp0);
                        ffma2(dot0[a], q0c[2 * j + 1], kp1);
                        ffma2(dot1[a], q1c[2 * j],     kp0);
                        ffma2(dot1[a], q1c[2 * j + 1], kp1);
                    }
                }
            }
        }

        const bool v0 = (kg < 7);
        const bool v1 = (kg >= dlt) && ((kg - dlt) < 7);
        float cs0 = 0.f, cs1 = 0.f;
#pragma unroll
        for (int a = 0; a < 7; a++) {
            float2 s0 = unpk2(dot0[a]);
            float2 s1 = unpk2(dot1[a]);
            if (v0) {
                const float e0 = __expf((s0.x + s0.y) * 0.125f);
                ss[q0t * SS_STRIDE + a * 7 + kg] = e0;
                cs0 += e0;
            }
            if (v1) {
                const float e1 = __expf((s1.x + s1.y) * 0.125f);
                ss[(q0t + 1) * SS_STRIDE + a * 7 + kg - dlt] = e1;
                cs1 += e1;
            }
        }
        cs0 += __shfl_xor_sync(0xffffffffu, cs0, 1);
        cs0 += __shfl_xor_sync(0xffffffffu, cs0, 2);
        cs0 += __shfl_xor_sync(0xffffffffu, cs0, 4);
        cs1 += __shfl_xor_sync(0xffffffffu, cs1, 1);
        cs1 += __shfl_xor_sync(0xffffffffu, cs1, 2);
        cs1 += __shfl_xor_sync(0xffffffffu, cs1, 4);
        if (kg == 0) {
            swsum[q0t]     = cs0;
            swsum[q0t + 1] = cs1;
        }
    }
    __syncthreads();

    // ================= AV phase: query pairs =================
    {
        const int sg  = tid & 7;            // 8-dim segment
        const int p   = tid >> 3;           // pair 0..31
        const int qy  = p >> 2, qxp = p & 3;
        const int qw0 = tw * 8 + qxp * 2;
        const int qhh = th * 8 + qy;
        const int sH  = min(max(qhh - 3, 0), 57);
        const int sW0 = min(max(qw0 - 3, 0), 57);
        const int sW1 = min(max(qw0 - 2, 0), 57);
        const int dlt = sW1 - sW0;
        const int UW  = dlt + 7;
        const int rH  = sH - sh0;
        const int rWu = sW0 - sw0;
        const int q0t = qy * 8 + qxp * 2;

        const float inv0 = 1.0f / swsum[q0t];
        const float inv1 = 1.0f / swsum[q0t + 1];

        u64 a0lo[2] = {0ull, 0ull}, a0hi[2] = {0ull, 0ull};
        u64 a1lo[2] = {0ull, 0ull}, a1hi[2] = {0ull, 0ull};

#pragma unroll
        for (int a = 0; a < 7; a++) {
#pragma unroll
            for (int cu = 0; cu < 8; cu++) {
                if (cu < UW) {
                    const int key = (rH + a) * KW + rWu + cu;
                    const float w0 = (cu < 7)
                        ? ss[q0t * SS_STRIDE + a * 7 + cu] : 0.f;
                    const float w1 = (cu >= dlt && (cu - dlt) < 7)
                        ? ss[(q0t + 1) * SS_STRIDE + a * 7 + cu - dlt] : 0.f;
                    const u64 w02 = dup2(w0), w12 = dup2(w1);
                    float4 vlo = *(const float4*)(sv + KV_W(key, sg));
                    float4 vhi = *(const float4*)(sv + KV_W(key, sg + 8));
                    const u64 vl0 = pack2(vlo.x, vlo.y), vl1 = pack2(vlo.z, vlo.w);
                    const u64 vh0 = pack2(vhi.x, vhi.y), vh1 = pack2(vhi.z, vhi.w);
                    ffma2(a0lo[0], w02, vl0); ffma2(a0lo[1], w02, vl1);
                    ffma2(a0hi[0], w02, vh0); ffma2(a0hi[1], w02, vh1);
                    ffma2(a1lo[0], w12, vl0); ffma2(a1lo[1], w12, vl1);
                    ffma2(a1hi[0], w12, vh0); ffma2(a1hi[1], w12, vh1);
                }
            }
        }

        const size_t ob0 = ((size_t)(b * SEQ + qhh * CAN + qw0)) * DMODEL + nh * DHEAD;
        const size_t ob1 = ob0 + DMODEL;    // adjacent query column

#define WRITE4(accA, accB, invv, base)                                      \
        {                                                                   \
            float2 pA = unpk2(accA), pB = unpk2(accB);                      \
            float vv[4] = {pA.x * (invv), pA.y * (invv),                    \
                           pB.x * (invv), pB.y * (invv)};                   \
            ushort4 h4;                                                     \
            u16* hp = &h4.x;                                                \
            _Pragma("unroll")                                               \
            for (int j = 0; j < 4; j++)                                     \
                hp[j] = hfbits(__float2half_rn(vv[j]));                     \
            *(ushort4*)(oh + (base)) = h4;                                  \
        }

        WRITE4(a0lo[0], a0lo[1], inv0, ob0 + sg * 4);
        WRITE4(a0hi[0], a0hi[1], inv0, ob0 + 32 + sg * 4);
        WRITE4(a1lo[0], a1lo[1], inv1, ob1 + sg * 4);
        WRITE4(a1hi[0], a1hi[1], inv1, ob1 + 32 + sg * 4);
#undef WRITE4
    }
}

// ---------------------------------------------------------------------------
extern "C" void kernel_launch(void* const* d_in, const int* in_sizes, int n_in,
                              void* d_out, int out_size)
{
    const float* x     = (const float*)d_in[0];   // [8192,512]
    const float* w_qkv = (const float*)d_in[1];   // [1536,512]
    const float* w_out = (const float*)d_in[2];   // [512,512]
    float* out = (float*)d_out;                   // [8192,512]

    float* qkv;
    __half *xh, *wqh, *woh, *ath;
    cudaGetSymbolAddress((void**)&qkv, g_qkv);
    cudaGetSymbolAddress((void**)&xh,  g_xh);
    cudaGetSymbolAddress((void**)&wqh, g_wqh);
    cudaGetSymbolAddress((void**)&woh, g_woh);
    cudaGetSymbolAddress((void**)&ath, g_ath);

    cudaFuncSetAttribute(gemm_mma, cudaFuncAttributeMaxDynamicSharedMemorySize, GEMM_SMEM);
    cudaFuncSetAttribute(nattn_kernel, cudaFuncAttributeMaxDynamicSharedMemorySize,
                         SMEM_ATTN_BYTES);

    const int M = BATCH * SEQ;  // 8192

    // 0) fused fp16 conversion of x, w_qkv, w_out (single launch)
    {
        const int total = N4_X + N4_WQ + N4_WO;
        split_all_kernel<<<(total + 255) / 256, 256>>>(x, w_qkv, w_out);
    }

    // 1) QKV projection: [8192,1536]
    gemm_mma<<<dim3((3 * DMODEL) / 128, M / 64), 256, GEMM_SMEM>>>(
        xh, wqh, qkv, M, 3 * DMODEL, DMODEL);

    // 2) neighborhood attention -> fp16 [8192,512]
    nattn_kernel<<<dim3(64, NHEADS, BATCH), 256, SMEM_ATTN_BYTES>>>(qkv, ath);

    // 3) output projection: [8192,512]
    gemm_mma<<<dim3(DMODEL / 128, M / 64), 256, GEMM_SMEM>>>(
        ath, woh, out, M, DMODEL, DMODEL);
}